// round 1
// baseline (speedup 1.0000x reference)
#include <cuda_runtime.h>

// Problem constants (fixed shapes per reference setup_inputs)
#define BB    4
#define HH    352
#define WW    1216
#define PLANE (HH * WW)        // 428032
#define NPIX  (BB * PLANE)     // 1712128

// Scratch: combined weights (f*softmax) and ping-pong x buffers.
// __device__ globals are the allocation-guard-safe scratch mechanism.
__device__ float g_w1[9 * NPIX];   // 61.6 MB
__device__ float g_w2[9 * NPIX];   // 61.6 MB
__device__ float g_xa[NPIX];       // 6.85 MB
__device__ float g_xb[NPIX];       // 6.85 MB

// ---------------------------------------------------------------------------
// prep: per-pixel 9-way softmax of guided1/guided2, scaled by fuse channels.
// Each thread handles 4 consecutive pixels (float4) of one batch image.
// ---------------------------------------------------------------------------
__global__ __launch_bounds__(256) void prep_kernel(
    const float* __restrict__ g1,
    const float* __restrict__ g2,
    const float* __restrict__ fu,
    float* __restrict__ w1,
    float* __restrict__ w2)
{
    int g = blockIdx.x * blockDim.x + threadIdx.x;
    if (g >= NPIX / 4) return;
    int b  = g / (PLANE / 4);
    int hw = (g - b * (PLANE / 4)) * 4;
    int base9 = b * 9 * PLANE + hw;
    int base2 = b * 2 * PLANE + hw;

    float a[9][4], c[9][4];
#pragma unroll
    for (int t = 0; t < 9; t++) {
        *(float4*)a[t] = *(const float4*)(g1 + base9 + t * PLANE);
        *(float4*)c[t] = *(const float4*)(g2 + base9 + t * PLANE);
    }
    float4 f1v = *(const float4*)(fu + base2);
    float4 f2v = *(const float4*)(fu + base2 + PLANE);
    float f1a[4] = {f1v.x, f1v.y, f1v.z, f1v.w};
    float f2a[4] = {f2v.x, f2v.y, f2v.z, f2v.w};

#pragma unroll
    for (int i = 0; i < 4; i++) {
        float m1 = a[0][i], m2 = c[0][i];
#pragma unroll
        for (int t = 1; t < 9; t++) {
            m1 = fmaxf(m1, a[t][i]);
            m2 = fmaxf(m2, c[t][i]);
        }
        float s1 = 0.f, s2 = 0.f;
#pragma unroll
        for (int t = 0; t < 9; t++) {
            float e1 = __expf(a[t][i] - m1); a[t][i] = e1; s1 += e1;
            float e2 = __expf(c[t][i] - m2); c[t][i] = e2; s2 += e2;
        }
        float r1 = f1a[i] / s1;
        float r2 = f2a[i] / s2;
#pragma unroll
        for (int t = 0; t < 9; t++) { a[t][i] *= r1; c[t][i] *= r2; }
    }
#pragma unroll
    for (int t = 0; t < 9; t++) {
        *(float4*)(w1 + base9 + t * PLANE) = *(float4*)a[t];
        *(float4*)(w2 + base9 + t * PLANE) = *(float4*)c[t];
    }
}

// ---------------------------------------------------------------------------
// prop: one propagation iteration.
//   x_new[p] = sum_t w1[t][p]*x[p + off1(t)] + sum_t w2[t][p]*x[p + off2(t)]
// off1: (kh-1, kw-1), off2: 2*(kh-1), 2*(kw-1), zero padding.
// Each thread computes 4 consecutive output pixels (float4 everywhere).
// Rows load 3 aligned float4 (cols w0-4 .. w0+7); out-of-range vectors are
// zero, which exactly implements the zero padding (W % 4 == 0).
// ---------------------------------------------------------------------------
__global__ __launch_bounds__(128) void prop_kernel(
    const float* __restrict__ xin,
    const float* __restrict__ w1,
    const float* __restrict__ w2,
    float* __restrict__ xout)
{
    int wg = blockIdx.x * blockDim.x + threadIdx.x;   // column group (4 px)
    int h  = blockIdx.y * blockDim.y + threadIdx.y;
    int b  = blockIdx.z;
    if (wg >= WW / 4 || h >= HH) return;
    int w0 = wg * 4;
    const float* xbm = xin + b * PLANE;

    // 5 rows (h-2..h+2) x 12 cols (w0-4..w0+7)
    float xr[5][12];
#pragma unroll
    for (int r = 0; r < 5; r++) {
        int hh = h + r - 2;
        bool rok = (hh >= 0) && (hh < HH);
        const float* rowp = xbm + hh * WW;
#pragma unroll
        for (int q = 0; q < 3; q++) {
            int c0 = w0 + (q - 1) * 4;
            float4 v = make_float4(0.f, 0.f, 0.f, 0.f);
            if (rok && c0 >= 0 && c0 < WW)
                v = *(const float4*)(rowp + c0);
            xr[r][q * 4 + 0] = v.x;
            xr[r][q * 4 + 1] = v.y;
            xr[r][q * 4 + 2] = v.z;
            xr[r][q * 4 + 3] = v.w;
        }
    }

    int p = b * 9 * PLANE + h * WW + w0;
    float acc0 = 0.f, acc1 = 0.f, acc2 = 0.f, acc3 = 0.f;

    // dilation-1 taps: row index in xr = 1+dr (dr=kh in 0..2), col = 3+i+dc
#pragma unroll
    for (int t = 0; t < 9; t++) {
        int dr = t / 3, dc = t % 3;
        float4 aw = *(const float4*)(w1 + p + t * PLANE);
        acc0 += aw.x * xr[1 + dr][3 + dc];
        acc1 += aw.y * xr[1 + dr][4 + dc];
        acc2 += aw.z * xr[1 + dr][5 + dc];
        acc3 += aw.w * xr[1 + dr][6 + dc];
    }
    // dilation-2 taps: row index = 2*dr (0,2,4), col = 2+i+2*dc
#pragma unroll
    for (int t = 0; t < 9; t++) {
        int dr = t / 3, dc = t % 3;
        float4 aw = *(const float4*)(w2 + p + t * PLANE);
        acc0 += aw.x * xr[2 * dr][2 + 2 * dc];
        acc1 += aw.y * xr[2 * dr][3 + 2 * dc];
        acc2 += aw.z * xr[2 * dr][4 + 2 * dc];
        acc3 += aw.w * xr[2 * dr][5 + 2 * dc];
    }

    *(float4*)(xout + b * PLANE + h * WW + w0) =
        make_float4(acc0, acc1, acc2, acc3);
}

// ---------------------------------------------------------------------------
// Launcher: prep once, then 8 propagation iterations ping-ponging through
// device-global scratch; final iteration writes d_out directly.
// Graph-capturable: kernel launches only (cudaGetSymbolAddress is a pure
// host-side query, not a stream operation).
// ---------------------------------------------------------------------------
extern "C" void kernel_launch(void* const* d_in, const int* in_sizes, int n_in,
                              void* d_out, int out_size)
{
    const float* g1 = (const float*)d_in[0];
    const float* g2 = (const float*)d_in[1];
    const float* fu = (const float*)d_in[2];
    const float* x0 = (const float*)d_in[3];
    float* out = (float*)d_out;

    float *w1, *w2, *xa, *xb;
    cudaGetSymbolAddress((void**)&w1, g_w1);
    cudaGetSymbolAddress((void**)&w2, g_w2);
    cudaGetSymbolAddress((void**)&xa, g_xa);
    cudaGetSymbolAddress((void**)&xb, g_xb);

    {
        int ngroups = NPIX / 4;
        prep_kernel<<<(ngroups + 255) / 256, 256>>>(g1, g2, fu, w1, w2);
    }

    dim3 blk(32, 4, 1);
    dim3 grd((WW / 4 + 31) / 32, (HH + 3) / 4, BB);

    const float* src = x0;
    float* dsts[8] = {xa, xb, xa, xb, xa, xb, xa, out};
    for (int i = 0; i < 8; i++) {
        prop_kernel<<<grd, blk>>>(src, w1, w2, dsts[i]);
        src = dsts[i];
    }
}

// round 2
// speedup vs baseline: 1.4235x; 1.4235x over previous
#include <cuda_runtime.h>

// Problem constants (fixed shapes per reference setup_inputs)
#define BB    4
#define HH    352
#define WW    1216
#define PLANE (HH * WW)        // 428032
#define NPIX  (BB * PLANE)     // 1712128

// Scratch: combined weights (f*softmax) and ping-pong x buffers.
__device__ float g_w1[9 * NPIX];   // 61.6 MB
__device__ float g_w2[9 * NPIX];   // 61.6 MB
__device__ float g_xa[NPIX];       // 6.85 MB
__device__ float g_xb[NPIX];       // 6.85 MB

// ---------------------------------------------------------------------------
// prep: per-pixel 9-way softmax of guided1/guided2, scaled by fuse channels.
// Each thread handles 4 consecutive pixels (float4) of one batch image.
// ---------------------------------------------------------------------------
__global__ __launch_bounds__(256) void prep_kernel(
    const float* __restrict__ g1,
    const float* __restrict__ g2,
    const float* __restrict__ fu,
    float* __restrict__ w1,
    float* __restrict__ w2)
{
    int g = blockIdx.x * blockDim.x + threadIdx.x;
    if (g >= NPIX / 4) return;
    int b  = g / (PLANE / 4);
    int hw = (g - b * (PLANE / 4)) * 4;
    int base9 = b * 9 * PLANE + hw;
    int base2 = b * 2 * PLANE + hw;

    float a[9][4], c[9][4];
#pragma unroll
    for (int t = 0; t < 9; t++) {
        *(float4*)a[t] = *(const float4*)(g1 + base9 + t * PLANE);
        *(float4*)c[t] = *(const float4*)(g2 + base9 + t * PLANE);
    }
    float4 f1v = *(const float4*)(fu + base2);
    float4 f2v = *(const float4*)(fu + base2 + PLANE);
    float f1a[4] = {f1v.x, f1v.y, f1v.z, f1v.w};
    float f2a[4] = {f2v.x, f2v.y, f2v.z, f2v.w};

#pragma unroll
    for (int i = 0; i < 4; i++) {
        float m1 = a[0][i], m2 = c[0][i];
#pragma unroll
        for (int t = 1; t < 9; t++) {
            m1 = fmaxf(m1, a[t][i]);
            m2 = fmaxf(m2, c[t][i]);
        }
        float s1 = 0.f, s2 = 0.f;
#pragma unroll
        for (int t = 0; t < 9; t++) {
            float e1 = __expf(a[t][i] - m1); a[t][i] = e1; s1 += e1;
            float e2 = __expf(c[t][i] - m2); c[t][i] = e2; s2 += e2;
        }
        float r1 = f1a[i] / s1;
        float r2 = f2a[i] / s2;
#pragma unroll
        for (int t = 0; t < 9; t++) { a[t][i] *= r1; c[t][i] *= r2; }
    }
#pragma unroll
    for (int t = 0; t < 9; t++) {
        *(float4*)(w1 + base9 + t * PLANE) = *(float4*)a[t];
        *(float4*)(w2 + base9 + t * PLANE) = *(float4*)c[t];
    }
}

// ---------------------------------------------------------------------------
// prop: one propagation iteration over NB batch images (pointers pre-offset).
//   x_new[p] = sum_t w1[t][p]*x[p + off1(t)] + sum_t w2[t][p]*x[p + off2(t)]
// off1: (kh-1, kw-1), off2: 2*(kh-1), 2*(kw-1), zero padding.
// Each thread computes 4 consecutive output pixels (float4 everywhere).
// ---------------------------------------------------------------------------
__global__ __launch_bounds__(128) void prop_kernel(
    const float* __restrict__ xin,
    const float* __restrict__ w1,
    const float* __restrict__ w2,
    float* __restrict__ xout)
{
    int wg = blockIdx.x * blockDim.x + threadIdx.x;   // column group (4 px)
    int h  = blockIdx.y * blockDim.y + threadIdx.y;
    int b  = blockIdx.z;                              // batch within this half
    if (wg >= WW / 4 || h >= HH) return;
    int w0 = wg * 4;
    const float* xbm = xin + b * PLANE;

    // 5 rows (h-2..h+2) x 12 cols (w0-4..w0+7)
    float xr[5][12];
#pragma unroll
    for (int r = 0; r < 5; r++) {
        int hh = h + r - 2;
        bool rok = (hh >= 0) && (hh < HH);
        const float* rowp = xbm + hh * WW;
#pragma unroll
        for (int q = 0; q < 3; q++) {
            int c0 = w0 + (q - 1) * 4;
            float4 v = make_float4(0.f, 0.f, 0.f, 0.f);
            if (rok && c0 >= 0 && c0 < WW)
                v = *(const float4*)(rowp + c0);
            xr[r][q * 4 + 0] = v.x;
            xr[r][q * 4 + 1] = v.y;
            xr[r][q * 4 + 2] = v.z;
            xr[r][q * 4 + 3] = v.w;
        }
    }

    int p = b * 9 * PLANE + h * WW + w0;
    float acc0 = 0.f, acc1 = 0.f, acc2 = 0.f, acc3 = 0.f;

    // dilation-1 taps: row index in xr = 1+dr, col = 3+i+dc
#pragma unroll
    for (int t = 0; t < 9; t++) {
        int dr = t / 3, dc = t % 3;
        float4 aw = *(const float4*)(w1 + p + t * PLANE);
        acc0 += aw.x * xr[1 + dr][3 + dc];
        acc1 += aw.y * xr[1 + dr][4 + dc];
        acc2 += aw.z * xr[1 + dr][5 + dc];
        acc3 += aw.w * xr[1 + dr][6 + dc];
    }
    // dilation-2 taps: row index = 2*dr (0,2,4), col = 2+i+2*dc
#pragma unroll
    for (int t = 0; t < 9; t++) {
        int dr = t / 3, dc = t % 3;
        float4 aw = *(const float4*)(w2 + p + t * PLANE);
        acc0 += aw.x * xr[2 * dr][2 + 2 * dc];
        acc1 += aw.y * xr[2 * dr][3 + 2 * dc];
        acc2 += aw.z * xr[2 * dr][4 + 2 * dc];
        acc3 += aw.w * xr[2 * dr][5 + 2 * dc];
    }

    *(float4*)(xout + b * PLANE + h * WW + w0) =
        make_float4(acc0, acc1, acc2, acc3);
}

// ---------------------------------------------------------------------------
// Launcher: prep once, then run the 8 propagation iterations per HALF-BATCH
// (2 images at a time) so the half's weights (61.6 MB) stay L2-resident
// across iterations. Half {2,3} first: prep's write order leaves the L2
// warm with the tail (b2/b3) weights.
// ---------------------------------------------------------------------------
extern "C" void kernel_launch(void* const* d_in, const int* in_sizes, int n_in,
                              void* d_out, int out_size)
{
    const float* g1 = (const float*)d_in[0];
    const float* g2 = (const float*)d_in[1];
    const float* fu = (const float*)d_in[2];
    const float* x0 = (const float*)d_in[3];
    float* out = (float*)d_out;

    float *w1, *w2, *xa, *xb;
    cudaGetSymbolAddress((void**)&w1, g_w1);
    cudaGetSymbolAddress((void**)&w2, g_w2);
    cudaGetSymbolAddress((void**)&xa, g_xa);
    cudaGetSymbolAddress((void**)&xb, g_xb);

    {
        int ngroups = NPIX / 4;
        prep_kernel<<<(ngroups + 255) / 256, 256>>>(g1, g2, fu, w1, w2);
    }

    const int NHALF = 2;                  // images per half
    dim3 blk(32, 4, 1);
    dim3 grd((WW / 4 + 31) / 32, (HH + 3) / 4, NHALF);

    int half_order[2] = {1, 0};           // half 1 = batches {2,3} first
    for (int hi = 0; hi < 2; hi++) {
        int hb   = half_order[hi];
        int boff = hb * NHALF;            // first batch index of this half
        const float* w1h = w1 + (size_t)boff * 9 * PLANE;
        const float* w2h = w2 + (size_t)boff * 9 * PLANE;
        float* xah = xa + (size_t)boff * PLANE;
        float* xbh = xb + (size_t)boff * PLANE;

        const float* src = x0 + (size_t)boff * PLANE;
        float* dsts[8] = {xah, xbh, xah, xbh, xah, xbh, xah,
                          out + (size_t)boff * PLANE};
        for (int i = 0; i < 8; i++) {
            prop_kernel<<<grd, blk>>>(src, w1h, w2h, dsts[i]);
            src = dsts[i];
        }
    }
}

// round 3
// speedup vs baseline: 2.0141x; 1.4149x over previous
#include <cuda_runtime.h>
#include <cuda_fp16.h>

// Problem constants (fixed shapes per reference setup_inputs)
#define BB    4
#define HH    352
#define WW    1216
#define PLANE (HH * WW)        // 428032
#define NPIX  (BB * PLANE)     // 1712128

// Scratch: combined weights (f*softmax) stored as fp16 (halves the dominant
// stream and lets the FULL batch working set fit in the 126 MB L2), plus
// fp32 ping-pong x buffers.
__device__ __half g_w1[9 * NPIX];  // 30.8 MB
__device__ __half g_w2[9 * NPIX];  // 30.8 MB
__device__ float  g_xa[NPIX];      // 6.85 MB
__device__ float  g_xb[NPIX];      // 6.85 MB

static __device__ __forceinline__ void store_half4(__half* p, const float* v) {
    __half2 lo = __floats2half2_rn(v[0], v[1]);
    __half2 hi = __floats2half2_rn(v[2], v[3]);
    uint2 u;
    u.x = *(const unsigned int*)&lo;
    u.y = *(const unsigned int*)&hi;
    *(uint2*)p = u;
}

static __device__ __forceinline__ void load_half4(const __half* p, float* v) {
    uint2 u = *(const uint2*)p;
    __half2 lo = *(const __half2*)&u.x;
    __half2 hi = *(const __half2*)&u.y;
    float2 f01 = __half22float2(lo);
    float2 f23 = __half22float2(hi);
    v[0] = f01.x; v[1] = f01.y; v[2] = f23.x; v[3] = f23.y;
}

// ---------------------------------------------------------------------------
// prep: per-pixel 9-way softmax of guided1/guided2, scaled by fuse channels,
// written as fp16. Each thread handles 4 consecutive pixels.
// ---------------------------------------------------------------------------
__global__ __launch_bounds__(256) void prep_kernel(
    const float* __restrict__ g1,
    const float* __restrict__ g2,
    const float* __restrict__ fu,
    __half* __restrict__ w1,
    __half* __restrict__ w2)
{
    int g = blockIdx.x * blockDim.x + threadIdx.x;
    if (g >= NPIX / 4) return;
    int b  = g / (PLANE / 4);
    int hw = (g - b * (PLANE / 4)) * 4;
    int base9 = b * 9 * PLANE + hw;
    int base2 = b * 2 * PLANE + hw;

    float a[9][4], c[9][4];
#pragma unroll
    for (int t = 0; t < 9; t++) {
        *(float4*)a[t] = *(const float4*)(g1 + base9 + t * PLANE);
        *(float4*)c[t] = *(const float4*)(g2 + base9 + t * PLANE);
    }
    float4 f1v = *(const float4*)(fu + base2);
    float4 f2v = *(const float4*)(fu + base2 + PLANE);
    float f1a[4] = {f1v.x, f1v.y, f1v.z, f1v.w};
    float f2a[4] = {f2v.x, f2v.y, f2v.z, f2v.w};

#pragma unroll
    for (int i = 0; i < 4; i++) {
        float m1 = a[0][i], m2 = c[0][i];
#pragma unroll
        for (int t = 1; t < 9; t++) {
            m1 = fmaxf(m1, a[t][i]);
            m2 = fmaxf(m2, c[t][i]);
        }
        float s1 = 0.f, s2 = 0.f;
#pragma unroll
        for (int t = 0; t < 9; t++) {
            float e1 = __expf(a[t][i] - m1); a[t][i] = e1; s1 += e1;
            float e2 = __expf(c[t][i] - m2); c[t][i] = e2; s2 += e2;
        }
        float r1 = f1a[i] / s1;
        float r2 = f2a[i] / s2;
#pragma unroll
        for (int t = 0; t < 9; t++) { a[t][i] *= r1; c[t][i] *= r2; }
    }
#pragma unroll
    for (int t = 0; t < 9; t++) {
        store_half4(w1 + base9 + t * PLANE, a[t]);
        store_half4(w2 + base9 + t * PLANE, c[t]);
    }
}

// ---------------------------------------------------------------------------
// prop: one propagation iteration over the full batch.
//   x_new[p] = sum_t w1[t][p]*x[p + off1(t)] + sum_t w2[t][p]*x[p + off2(t)]
// off1: (kh-1, kw-1), off2: 2*(kh-1), 2*(kw-1), zero padding.
// Each thread computes 4 consecutive output pixels.
// ---------------------------------------------------------------------------
__global__ __launch_bounds__(256) void prop_kernel(
    const float* __restrict__ xin,
    const __half* __restrict__ w1,
    const __half* __restrict__ w2,
    float* __restrict__ xout)
{
    int wg = blockIdx.x * blockDim.x + threadIdx.x;   // column group (4 px)
    int h  = blockIdx.y * blockDim.y + threadIdx.y;
    int b  = blockIdx.z;
    if (wg >= WW / 4 || h >= HH) return;
    int w0 = wg * 4;
    const float* xbm = xin + b * PLANE;

    // 5 rows (h-2..h+2) x 12 cols (w0-4..w0+7)
    float xr[5][12];
#pragma unroll
    for (int r = 0; r < 5; r++) {
        int hh = h + r - 2;
        bool rok = (hh >= 0) && (hh < HH);
        const float* rowp = xbm + hh * WW;
#pragma unroll
        for (int q = 0; q < 3; q++) {
            int c0 = w0 + (q - 1) * 4;
            float4 v = make_float4(0.f, 0.f, 0.f, 0.f);
            if (rok && c0 >= 0 && c0 < WW)
                v = *(const float4*)(rowp + c0);
            xr[r][q * 4 + 0] = v.x;
            xr[r][q * 4 + 1] = v.y;
            xr[r][q * 4 + 2] = v.z;
            xr[r][q * 4 + 3] = v.w;
        }
    }

    int p = b * 9 * PLANE + h * WW + w0;
    float acc0 = 0.f, acc1 = 0.f, acc2 = 0.f, acc3 = 0.f;

    // dilation-1 taps: row index in xr = 1+dr, col = 3+i+dc
#pragma unroll
    for (int t = 0; t < 9; t++) {
        int dr = t / 3, dc = t % 3;
        float aw[4];
        load_half4(w1 + p + t * PLANE, aw);
        acc0 += aw[0] * xr[1 + dr][3 + dc];
        acc1 += aw[1] * xr[1 + dr][4 + dc];
        acc2 += aw[2] * xr[1 + dr][5 + dc];
        acc3 += aw[3] * xr[1 + dr][6 + dc];
    }
    // dilation-2 taps: row index = 2*dr (0,2,4), col = 2+i+2*dc
#pragma unroll
    for (int t = 0; t < 9; t++) {
        int dr = t / 3, dc = t % 3;
        float aw[4];
        load_half4(w2 + p + t * PLANE, aw);
        acc0 += aw[0] * xr[2 * dr][2 + 2 * dc];
        acc1 += aw[1] * xr[2 * dr][3 + 2 * dc];
        acc2 += aw[2] * xr[2 * dr][4 + 2 * dc];
        acc3 += aw[3] * xr[2 * dr][5 + 2 * dc];
    }

    *(float4*)(xout + b * PLANE + h * WW + w0) =
        make_float4(acc0, acc1, acc2, acc3);
}

// ---------------------------------------------------------------------------
// Launcher: prep once, then 8 full-batch propagation iterations. With fp16
// weights the whole working set (61.6 MB weights + 20 MB x) is L2-resident,
// so only iteration 1 pays DRAM for the weights.
// ---------------------------------------------------------------------------
extern "C" void kernel_launch(void* const* d_in, const int* in_sizes, int n_in,
                              void* d_out, int out_size)
{
    const float* g1 = (const float*)d_in[0];
    const float* g2 = (const float*)d_in[1];
    const float* fu = (const float*)d_in[2];
    const float* x0 = (const float*)d_in[3];
    float* out = (float*)d_out;

    __half *w1, *w2;
    float *xa, *xb;
    cudaGetSymbolAddress((void**)&w1, g_w1);
    cudaGetSymbolAddress((void**)&w2, g_w2);
    cudaGetSymbolAddress((void**)&xa, g_xa);
    cudaGetSymbolAddress((void**)&xb, g_xb);

    {
        int ngroups = NPIX / 4;
        prep_kernel<<<(ngroups + 255) / 256, 256>>>(g1, g2, fu, w1, w2);
    }

    dim3 blk(32, 8, 1);
    dim3 grd((WW / 4 + 31) / 32, (HH + 7) / 8, BB);

    const float* src = x0;
    float* dsts[8] = {xa, xb, xa, xb, xa, xb, xa, out};
    for (int i = 0; i < 8; i++) {
        prop_kernel<<<grd, blk>>>(src, w1, w2, dsts[i]);
        src = dsts[i];
    }
}

// round 4
// speedup vs baseline: 2.0460x; 1.0159x over previous
#include <cuda_runtime.h>
#include <cuda_fp16.h>

// Problem constants (fixed shapes per reference setup_inputs)
#define BB    4
#define HH    352
#define WW    1216
#define PLANE (HH * WW)        // 428032
#define NPIX  (BB * PLANE)     // 1712128
#define NGRP  (NPIX / 4)       // 428032 4-pixel groups (divisible by 32)

// Weight records: one 144-B record per 4-pixel group = 9 x uint4.
// uint4 j holds { w1[tap j] px0..3 (4 half), w2[tap j] px0..3 (4 half) }.
// Swizzled tap-major within 32-group blocks for perfect warp coalescing:
//   idx(g, j) = (g>>5)*288 + j*32 + (g&31)
__device__ uint4 g_wrec[(size_t)NGRP * 9];   // 61.6 MB
__device__ float g_xa[NPIX];                 // 6.85 MB
__device__ float g_xb[NPIX];                 // 6.85 MB

static __device__ __forceinline__ size_t widx(int g, int j) {
    return (size_t)(g >> 5) * 288 + j * 32 + (g & 31);
}

// Load the 5x12 x-window (rows h-2..h+2, cols w0-4..w0+7) with zero padding.
static __device__ __forceinline__ void load_xwin(
    const float* __restrict__ xbm, int h, int w0, float xr[5][12])
{
#pragma unroll
    for (int r = 0; r < 5; r++) {
        int hh = h + r - 2;
        bool rok = (hh >= 0) && (hh < HH);
        const float* rowp = xbm + hh * WW;
#pragma unroll
        for (int q = 0; q < 3; q++) {
            int c0 = w0 + (q - 1) * 4;
            float4 v = make_float4(0.f, 0.f, 0.f, 0.f);
            if (rok && c0 >= 0 && c0 < WW)
                v = *(const float4*)(rowp + c0);
            xr[r][q * 4 + 0] = v.x;
            xr[r][q * 4 + 1] = v.y;
            xr[r][q * 4 + 2] = v.z;
            xr[r][q * 4 + 3] = v.w;
        }
    }
}

// Apply one weight record uint4 (tap j, both dilations) to the accumulators.
static __device__ __forceinline__ void apply_tap(
    uint4 r, int j, const float xr[5][12],
    float& acc0, float& acc1, float& acc2, float& acc3)
{
    int dr = j / 3, dc = j % 3;
    float2 a01 = __half22float2(*(const __half2*)&r.x);
    float2 a23 = __half22float2(*(const __half2*)&r.y);
    float2 b01 = __half22float2(*(const __half2*)&r.z);
    float2 b23 = __half22float2(*(const __half2*)&r.w);
    // dilation-1: row 1+dr, col 3+i+dc
    acc0 += a01.x * xr[1 + dr][3 + dc];
    acc1 += a01.y * xr[1 + dr][4 + dc];
    acc2 += a23.x * xr[1 + dr][5 + dc];
    acc3 += a23.y * xr[1 + dr][6 + dc];
    // dilation-2: row 2*dr, col 2+i+2*dc
    acc0 += b01.x * xr[2 * dr][2 + 2 * dc];
    acc1 += b01.y * xr[2 * dr][3 + 2 * dc];
    acc2 += b23.x * xr[2 * dr][4 + 2 * dc];
    acc3 += b23.y * xr[2 * dr][5 + 2 * dc];
}

// ---------------------------------------------------------------------------
// prop_first: fused softmax + weight-record write + propagation iteration 1.
// One thread per 4-pixel group (1D over NGRP).
// ---------------------------------------------------------------------------
__global__ __launch_bounds__(256) void prop_first_kernel(
    const float* __restrict__ g1,
    const float* __restrict__ g2,
    const float* __restrict__ fu,
    const float* __restrict__ x0,
    uint4* __restrict__ wrec,
    float* __restrict__ xout)
{
    int g = blockIdx.x * blockDim.x + threadIdx.x;
    if (g >= NGRP) return;
    int b   = g / (PLANE / 4);
    int rem = g - b * (PLANE / 4);
    int h   = rem / (WW / 4);
    int w0  = (rem - h * (WW / 4)) * 4;
    int hw  = rem * 4;
    int base9 = b * 9 * PLANE + hw;
    int base2 = b * 2 * PLANE + hw;

    // --- softmax of both guides, scaled by fuse ---
    float a[9][4], c[9][4];
#pragma unroll
    for (int t = 0; t < 9; t++) {
        *(float4*)a[t] = *(const float4*)(g1 + base9 + t * PLANE);
        *(float4*)c[t] = *(const float4*)(g2 + base9 + t * PLANE);
    }
    float4 f1v = *(const float4*)(fu + base2);
    float4 f2v = *(const float4*)(fu + base2 + PLANE);
    float f1a[4] = {f1v.x, f1v.y, f1v.z, f1v.w};
    float f2a[4] = {f2v.x, f2v.y, f2v.z, f2v.w};

#pragma unroll
    for (int i = 0; i < 4; i++) {
        float m1 = a[0][i], m2 = c[0][i];
#pragma unroll
        for (int t = 1; t < 9; t++) {
            m1 = fmaxf(m1, a[t][i]);
            m2 = fmaxf(m2, c[t][i]);
        }
        float s1 = 0.f, s2 = 0.f;
#pragma unroll
        for (int t = 0; t < 9; t++) {
            float e1 = __expf(a[t][i] - m1); a[t][i] = e1; s1 += e1;
            float e2 = __expf(c[t][i] - m2); c[t][i] = e2; s2 += e2;
        }
        float r1 = f1a[i] / s1;
        float r2 = f2a[i] / s2;
#pragma unroll
        for (int t = 0; t < 9; t++) { a[t][i] *= r1; c[t][i] *= r2; }
    }

    // --- pack into fp16 records; a/c die here ---
    uint4 rec[9];
#pragma unroll
    for (int j = 0; j < 9; j++) {
        __half2 ha = __floats2half2_rn(a[j][0], a[j][1]);
        __half2 hb = __floats2half2_rn(a[j][2], a[j][3]);
        __half2 hc = __floats2half2_rn(c[j][0], c[j][1]);
        __half2 hd = __floats2half2_rn(c[j][2], c[j][3]);
        rec[j].x = *(const unsigned int*)&ha;
        rec[j].y = *(const unsigned int*)&hb;
        rec[j].z = *(const unsigned int*)&hc;
        rec[j].w = *(const unsigned int*)&hd;
        wrec[widx(g, j)] = rec[j];
    }

    // --- propagation iteration 1 using the fresh (fp16-rounded) weights ---
    float xr[5][12];
    load_xwin(x0 + b * PLANE, h, w0, xr);

    float acc0 = 0.f, acc1 = 0.f, acc2 = 0.f, acc3 = 0.f;
#pragma unroll
    for (int j = 0; j < 9; j++)
        apply_tap(rec[j], j, xr, acc0, acc1, acc2, acc3);

    *(float4*)(xout + b * PLANE + h * WW + w0) =
        make_float4(acc0, acc1, acc2, acc3);
}

// ---------------------------------------------------------------------------
// prop: one warm propagation iteration. One thread per 4-pixel group.
// 9 perfectly-coalesced LDG.128 weight loads per thread.
// ---------------------------------------------------------------------------
__global__ __launch_bounds__(256) void prop_kernel(
    const float* __restrict__ xin,
    const uint4* __restrict__ wrec,
    float* __restrict__ xout)
{
    int g = blockIdx.x * blockDim.x + threadIdx.x;
    if (g >= NGRP) return;
    int b   = g / (PLANE / 4);
    int rem = g - b * (PLANE / 4);
    int h   = rem / (WW / 4);
    int w0  = (rem - h * (WW / 4)) * 4;

    float xr[5][12];
    load_xwin(xin + b * PLANE, h, w0, xr);

    float acc0 = 0.f, acc1 = 0.f, acc2 = 0.f, acc3 = 0.f;
#pragma unroll
    for (int j = 0; j < 9; j++) {
        uint4 r = wrec[widx(g, j)];
        apply_tap(r, j, xr, acc0, acc1, acc2, acc3);
    }

    *(float4*)(xout + b * PLANE + h * WW + w0) =
        make_float4(acc0, acc1, acc2, acc3);
}

// ---------------------------------------------------------------------------
// Launcher: fused first iteration (softmax + write records + prop1), then
// 7 warm iterations reading the L2-resident records.
// ---------------------------------------------------------------------------
extern "C" void kernel_launch(void* const* d_in, const int* in_sizes, int n_in,
                              void* d_out, int out_size)
{
    const float* g1 = (const float*)d_in[0];
    const float* g2 = (const float*)d_in[1];
    const float* fu = (const float*)d_in[2];
    const float* x0 = (const float*)d_in[3];
    float* out = (float*)d_out;

    uint4* wrec;
    float *xa, *xb;
    cudaGetSymbolAddress((void**)&wrec, g_wrec);
    cudaGetSymbolAddress((void**)&xa, g_xa);
    cudaGetSymbolAddress((void**)&xb, g_xb);

    int nblk = (NGRP + 255) / 256;
    prop_first_kernel<<<nblk, 256>>>(g1, g2, fu, x0, wrec, xa);

    const float* src = xa;
    float* dsts[7] = {xb, xa, xb, xa, xb, xa, out};
    for (int i = 0; i < 7; i++) {
        prop_kernel<<<nblk, 256>>>(src, wrec, dsts[i]);
        src = dsts[i];
    }
}

// round 5
// speedup vs baseline: 2.1518x; 1.0517x over previous
#include <cuda_runtime.h>
#include <cuda_fp16.h>

// Problem constants (fixed shapes per reference setup_inputs)
#define BB    4
#define HH    352            // = 16 * 22
#define WW    1216           // = 4 * 304, 304 = 16 * 19
#define PLANE (HH * WW)      // 428032
#define NPIX  (BB * PLANE)   // 1712128
#define NGRP  (NPIX / 4)     // 428032 4-pixel groups

// Grid geometry shared by prep and prop so record ids agree:
//   grid = (19, 22, 4); prop block = (16,16) [group-in-row, row]; 256 rec/blk
#define GX 19
#define GY 22

// Weight records: one 144-B record per 4-pixel group = 9 x uint4.
// uint4 j = { w1 px01, w2 px01, w1 px23, w2 px23 } (each 2 halves).
// Tap-major swizzle within 32-record blocks, indexed by launch-flat tid:
//   idx(g, j) = (g>>5)*288 + j*32 + (g&31)
__device__ uint4 g_wrec[(size_t)NGRP * 9];   // 61.6 MB
__device__ float g_xa[NPIX];                 // 6.85 MB
__device__ float g_xb[NPIX];                 // 6.85 MB

static __device__ __forceinline__ size_t widx(int g, int j) {
    return (size_t)(g >> 5) * 288 + j * 32 + (g & 31);
}

// ---------------------------------------------------------------------------
// prep: per-pixel 9-way softmax of guided1/guided2, scaled by fuse channels.
// 512-thread blocks; each thread handles 2 pixels (half a 4-px record).
// tid mapping: tz = tid&1 (half-record), tx = (tid>>1)&15, ty = tid>>5.
// ---------------------------------------------------------------------------
__global__ __launch_bounds__(512) void prep_kernel(
    const float* __restrict__ g1,
    const float* __restrict__ g2,
    const float* __restrict__ fu,
    uint4* __restrict__ wrec)
{
    int tid = threadIdx.x;
    int tz = tid & 1;
    int tx = (tid >> 1) & 15;
    int ty = tid >> 5;

    int bx = blockIdx.x, by = blockIdx.y, b = blockIdx.z;
    int gw = bx * 16 + tx;           // 4-px group within row
    int h  = by * 16 + ty;

    // launch-flat record id (must match prop's mapping)
    int g = ((b * GY + by) * GX + bx) * 256 + ty * 16 + tx;

    int px    = h * WW + gw * 4 + tz * 2;
    int base9 = b * 9 * PLANE + px;
    int base2 = b * 2 * PLANE + px;

    float a[9][2], c[9][2];
#pragma unroll
    for (int t = 0; t < 9; t++) {
        *(float2*)a[t] = *(const float2*)(g1 + base9 + t * PLANE);
        *(float2*)c[t] = *(const float2*)(g2 + base9 + t * PLANE);
    }
    float2 f1v = *(const float2*)(fu + base2);
    float2 f2v = *(const float2*)(fu + base2 + PLANE);
    float f1a[2] = {f1v.x, f1v.y};
    float f2a[2] = {f2v.x, f2v.y};

#pragma unroll
    for (int i = 0; i < 2; i++) {
        float m1 = a[0][i], m2 = c[0][i];
#pragma unroll
        for (int t = 1; t < 9; t++) {
            m1 = fmaxf(m1, a[t][i]);
            m2 = fmaxf(m2, c[t][i]);
        }
        float s1 = 0.f, s2 = 0.f;
#pragma unroll
        for (int t = 0; t < 9; t++) {
            float e1 = __expf(a[t][i] - m1); a[t][i] = e1; s1 += e1;
            float e2 = __expf(c[t][i] - m2); c[t][i] = e2; s2 += e2;
        }
        float r1 = f1a[i] / s1;
        float r2 = f2a[i] / s2;
#pragma unroll
        for (int t = 0; t < 9; t++) { a[t][i] *= r1; c[t][i] *= r2; }
    }

    // Write this thread's half-record for each tap: {w1 px-pair, w2 px-pair}.
#pragma unroll
    for (int j = 0; j < 9; j++) {
        __half2 hw1 = __floats2half2_rn(a[j][0], a[j][1]);
        __half2 hw2 = __floats2half2_rn(c[j][0], c[j][1]);
        uint2 u;
        u.x = *(const unsigned int*)&hw1;
        u.y = *(const unsigned int*)&hw2;
        ((uint2*)&wrec[widx(g, j)])[tz] = u;
    }
}

// ---------------------------------------------------------------------------
// prop: one propagation iteration. Block (16,16): 64 px x 16 rows tile so
// the 5-row x window is reused vertically within the block (L1-resident).
// Weights read with __ldcg (L2-cached, L1-bypassed: read-once per iter).
// ---------------------------------------------------------------------------
__global__ __launch_bounds__(256) void prop_kernel(
    const float* __restrict__ xin,
    const uint4* __restrict__ wrec,
    float* __restrict__ xout)
{
    int tx = threadIdx.x, ty = threadIdx.y;
    int bx = blockIdx.x, by = blockIdx.y, b = blockIdx.z;
    int gw = bx * 16 + tx;
    int h  = by * 16 + ty;
    int w0 = gw * 4;
    int g  = ((b * GY + by) * GX + bx) * 256 + ty * 16 + tx;

    const float* xbm = xin + b * PLANE;

    // Issue the 9 weight loads first (independent, coalesced, L2-bound).
    uint4 rec[9];
#pragma unroll
    for (int j = 0; j < 9; j++)
        rec[j] = __ldcg(&wrec[widx(g, j)]);

    // 5 rows (h-2..h+2) x 12 cols (w0-4..w0+7), zero-padded.
    float xr[5][12];
#pragma unroll
    for (int r = 0; r < 5; r++) {
        int hh = h + r - 2;
        bool rok = (hh >= 0) && (hh < HH);
        const float* rowp = xbm + hh * WW;
#pragma unroll
        for (int q = 0; q < 3; q++) {
            int c0 = w0 + (q - 1) * 4;
            float4 v = make_float4(0.f, 0.f, 0.f, 0.f);
            if (rok && c0 >= 0 && c0 < WW)
                v = *(const float4*)(rowp + c0);
            xr[r][q * 4 + 0] = v.x;
            xr[r][q * 4 + 1] = v.y;
            xr[r][q * 4 + 2] = v.z;
            xr[r][q * 4 + 3] = v.w;
        }
    }

    float acc0 = 0.f, acc1 = 0.f, acc2 = 0.f, acc3 = 0.f;
#pragma unroll
    for (int j = 0; j < 9; j++) {
        int dr = j / 3, dc = j % 3;
        float2 a01 = __half22float2(*(const __half2*)&rec[j].x);  // w1 px0,1
        float2 b01 = __half22float2(*(const __half2*)&rec[j].y);  // w2 px0,1
        float2 a23 = __half22float2(*(const __half2*)&rec[j].z);  // w1 px2,3
        float2 b23 = __half22float2(*(const __half2*)&rec[j].w);  // w2 px2,3
        // dilation-1: row 1+dr, col 3+i+dc
        acc0 += a01.x * xr[1 + dr][3 + dc];
        acc1 += a01.y * xr[1 + dr][4 + dc];
        acc2 += a23.x * xr[1 + dr][5 + dc];
        acc3 += a23.y * xr[1 + dr][6 + dc];
        // dilation-2: row 2*dr, col 2+i+2*dc
        acc0 += b01.x * xr[2 * dr][2 + 2 * dc];
        acc1 += b01.y * xr[2 * dr][3 + 2 * dc];
        acc2 += b23.x * xr[2 * dr][4 + 2 * dc];
        acc3 += b23.y * xr[2 * dr][5 + 2 * dc];
    }

    *(float4*)(xout + b * PLANE + h * WW + w0) =
        make_float4(acc0, acc1, acc2, acc3);
}

// ---------------------------------------------------------------------------
// Launcher: lean prep (DRAM-stream), then 8 propagation iterations reading
// the L2-resident fp16 weight records.
// ---------------------------------------------------------------------------
extern "C" void kernel_launch(void* const* d_in, const int* in_sizes, int n_in,
                              void* d_out, int out_size)
{
    const float* g1 = (const float*)d_in[0];
    const float* g2 = (const float*)d_in[1];
    const float* fu = (const float*)d_in[2];
    const float* x0 = (const float*)d_in[3];
    float* out = (float*)d_out;

    uint4* wrec;
    float *xa, *xb;
    cudaGetSymbolAddress((void**)&wrec, g_wrec);
    cudaGetSymbolAddress((void**)&xa, g_xa);
    cudaGetSymbolAddress((void**)&xb, g_xb);

    dim3 grd(GX, GY, BB);
    prep_kernel<<<grd, 512>>>(g1, g2, fu, wrec);

    dim3 pblk(16, 16, 1);
    const float* src = x0;
    float* dsts[8] = {xa, xb, xa, xb, xa, xb, xa, out};
    for (int i = 0; i < 8; i++) {
        prop_kernel<<<grd, pblk>>>(src, wrec, dsts[i]);
        src = dsts[i];
    }
}